// round 13
// baseline (speedup 1.0000x reference)
#include <cuda_runtime.h>
#include <cuda_bf16.h>
#include <math_constants.h>
#include <stdint.h>

#define B_  2048
#define E_  128
#define V_  100000
#define NT_ 782   // ceil(V/128)
#define MT_ 16    // B/128
#define PAD_ 96.0f   // NT_*128 - V_

#define LOG2E_ 1.4426950408889634f
#define LN2_   0.6931471805599453f

#define LDSA 136                     // smem row stride in bf16 (128 + 8 pad)
#define TILE_BYTES (128 * LDSA * 2)  // 34816 per tile buffer
#define SM_A0 0
#define SM_A1 TILE_BYTES
#define SM_B  (2 * TILE_BYTES)
#define SM_BO (3 * TILE_BYTES)             // 512 B bias (permuted, pre-scaled)
#define SMEM_BYTES (3 * TILE_BYTES + 512)  // 104960

// column permutation: c=(j2,j1,j0,q1,q0,e) -> g=(j2,q1,q0,j1,j0,e)
// makes each lane's 4 bf16x2 epilogue values 8 consecutive global columns.
#define PERM6(c) (((c) & 0x21) | (((c) & 0x06) << 2) | (((c) & 0x18) >> 2))

// ---- scratch (no allocation allowed; device globals) ----
__device__ __nv_bfloat16 g_embb[B_ * E_];            // emb * log2e, bf16
__device__ __nv_bfloat16 g_woutb[(size_t)V_ * E_];   // W_out bf16 (25.6 MB)
__device__ __nv_bfloat16 g_logits[(size_t)B_ * V_];  // bf16 scaled logits (logit*log2e)
__device__ float g_psum[(size_t)NT_ * 2 * B_];       // [ntile][wn][row] sumexp partials
__device__ float g_lse[B_];
__device__ int   g_is64;

// ================= helpers =================
__device__ __forceinline__ uint32_t smem_u32(const void* p) {
    uint32_t a;
    asm("{ .reg .u64 t; cvta.to.shared.u64 t, %1; cvt.u32.u64 %0, t; }" : "=r"(a) : "l"(p));
    return a;
}
__device__ __forceinline__ float ex2(float x) {
    float y;
    asm("ex2.approx.ftz.f32 %0, %1;" : "=f"(y) : "f"(x));
    return y;
}
__device__ __forceinline__ void cp16(uint32_t dst, const void* src) {
    asm volatile("cp.async.cg.shared.global [%0], [%1], 16;" :: "r"(dst), "l"(src));
}
__device__ __forceinline__ void cp16z(uint32_t dst, const void* src, int bytes) {
    asm volatile("cp.async.cg.shared.global [%0], [%1], 16, %2;"
                 :: "r"(dst), "l"(src), "r"(bytes));
}
#define CP_COMMIT() asm volatile("cp.async.commit_group;" ::: "memory")
#define CP_WAIT0()  asm volatile("cp.async.wait_group 0;" ::: "memory")

__device__ __forceinline__ void ldsm4(uint32_t* d, uint32_t a) {
    asm volatile("ldmatrix.sync.aligned.m8n8.x4.shared.b16 {%0,%1,%2,%3}, [%4];"
        : "=r"(d[0]), "=r"(d[1]), "=r"(d[2]), "=r"(d[3]) : "r"(a));
}
__device__ __forceinline__ void mma16816(float* c, const uint32_t* a, const uint32_t* b) {
    asm volatile("mma.sync.aligned.m16n8k16.row.col.f32.bf16.bf16.f32 "
        "{%0,%1,%2,%3}, {%4,%5,%6,%7}, {%8,%9}, {%0,%1,%2,%3};"
        : "+f"(c[0]), "+f"(c[1]), "+f"(c[2]), "+f"(c[3])
        : "r"(a[0]), "r"(a[1]), "r"(a[2]), "r"(a[3]), "r"(b[0]), "r"(b[1]));
}

// ---- dtype detection for center_word (jax int64 may actually be int32) ----
__global__ void k_detect(const void* __restrict__ cw) {
    __shared__ int ok;
    if (threadIdx.x == 0) ok = 1;
    __syncthreads();
    const int2* p = (const int2*)cw;
    int bad = 0;
    for (int i = threadIdx.x; i < 1024; i += 256) {
        int2 v = p[i];
        if (v.y != 0 || v.x < 0 || v.x >= V_) bad = 1;
    }
    if (bad) atomicAnd(&ok, 0);
    __syncthreads();
    if (threadIdx.x == 0) g_is64 = ok;
}

// emb scaled by log2e so the epilogue exp becomes a bare ex2
__global__ void k_gather(const void* __restrict__ cw,
                         const float* __restrict__ Wc,
                         const float* __restrict__ bc) {
    int b = blockIdx.x, e = threadIdx.x;
    long long idx;
    if (g_is64) idx = ((const long long*)cw)[b];
    else        idx = (long long)(((const int*)cw)[b]);
    float v = (Wc[(size_t)e * V_ + idx] + bc[e]) * LOG2E_;
    g_embb[b * E_ + e] = __float2bfloat16(v);
}

__global__ void k_cvt(const float* __restrict__ W) {
    size_t i = (size_t)blockIdx.x * blockDim.x + threadIdx.x;
    const size_t n4 = (size_t)V_ * E_ / 4;
    if (i >= n4) return;
    float4 f = ((const float4*)W)[i];
    __nv_bfloat162* o = (__nv_bfloat162*)g_woutb;
    o[2 * i + 0] = __floats2bfloat162_rn(f.x, f.y);
    o[2 * i + 1] = __floats2bfloat162_rn(f.z, f.w);
}

// ================= single GEMM pass =================
// One CTA per N-tile (128 cols of V), persistent over 16 M-tiles.
// 8 warps: 4(M) x 2(N); full warp tile 32M x 64N (acc[2][8][4]), 2 CTAs/SM.
// A double-buffered (prefetch before mainloop, wait after epilogue).
// B rows loaded PERMUTED (PERM6): direct STG.128 logit stores from registers.
// Row partials: 2 shuffles then 8 q==0 lanes store 32B coalesced straight to
// g_psum[ntile][wn][*] -- no smem funnel, ONE __syncthreads per M-tile (the
// A-buffer swap). Pad cols contribute ex2(0)=1; k_lse subtracts PAD_.
__global__ void __launch_bounds__(256, 2)
k_gemm(const float* __restrict__ b_out) {
    extern __shared__ __align__(1024) char smem[];
    const uint32_t sb = smem_u32(smem);
    float* bo_s = (float*)(smem + SM_BO);

    const int ntile = blockIdx.x;
    const int n0 = ntile * 128;
    const int tid = threadIdx.x, lane = tid & 31, wid = tid >> 5;
    const int wm = wid >> 1, wn = wid & 1;

    // permuted bias (pre-scaled by log2e); pad cols -> 0
    if (tid < 128) {
        int gcol = n0 + (tid & 64) + PERM6(tid & 63);
        bo_s[tid] = (gcol < V_) ? b_out[gcol] * LOG2E_ : 0.f;
    }

    // ---- B tile (once, permuted rows) + A tile 0 ----
    #pragma unroll
    for (int li = tid; li < 2048; li += 256) {
        int r = li >> 4, c = li & 15;
        int v = n0 + (r & 64) + PERM6(r & 63);
        cp16z(sb + SM_B + (uint32_t)r * (LDSA * 2) + c * 16,
              g_woutb + (size_t)(v < V_ ? v : 0) * E_ + c * 8, (v < V_) ? 16 : 0);
    }
    #pragma unroll
    for (int li = tid; li < 2048; li += 256) {
        int r = li >> 4, c = li & 15;
        cp16(sb + SM_A0 + (uint32_t)r * (LDSA * 2) + c * 16,
             g_embb + (size_t)r * E_ + c * 8);
    }
    CP_COMMIT();
    CP_WAIT0();
    __syncthreads();

    const uint32_t a_lane = (uint32_t)(wm * 32 + (lane & 15)) * (LDSA * 2)
                          + ((lane >> 4) << 3) * 2;
    const uint32_t b_rowb = sb + SM_B
                          + (uint32_t)(wn * 64 + (lane & 7) + ((lane >> 4) << 3)) * (LDSA * 2)
                          + (((lane >> 3) & 1) << 3) * 2;
    const int qrow = lane >> 2, q = lane & 3;
    float* psum_base = g_psum + ((size_t)ntile * 2 + wn) * B_;

    for (int it = 0; it < MT_; it++) {
        const int m0 = it * 128;
        const uint32_t a_base = sb + ((it & 1) ? SM_A1 : SM_A0) + a_lane;

        // prefetch next A tile into the other buffer (hidden under mainloop)
        if (it + 1 < MT_) {
            const uint32_t nb = sb + ((it & 1) ? SM_A0 : SM_A1);
            #pragma unroll
            for (int li = tid; li < 2048; li += 256) {
                int r = li >> 4, c = li & 15;
                cp16(nb + (uint32_t)r * (LDSA * 2) + c * 16,
                     g_embb + (size_t)(m0 + 128 + r) * E_ + c * 8);
            }
        }
        CP_COMMIT();

        // ---- mainloop: 128x128x128, full 32Mx64N warp tile ----
        float acc[2][8][4];
        #pragma unroll
        for (int i = 0; i < 2; i++)
            #pragma unroll
            for (int j = 0; j < 8; j++)
                #pragma unroll
                for (int k = 0; k < 4; k++) acc[i][j][k] = 0.f;

        #pragma unroll
        for (int ks = 0; ks < 8; ks++) {
            const uint32_t koff = (uint32_t)(ks * 16) * 2;
            uint32_t a0[4], a1[4], bb[4][4];
            ldsm4(a0, a_base + koff);
            ldsm4(a1, a_base + 16 * (LDSA * 2) + koff);
            #pragma unroll
            for (int nfp = 0; nfp < 4; nfp++)
                ldsm4(bb[nfp], b_rowb + (uint32_t)(nfp * 16) * (LDSA * 2) + koff);
            #pragma unroll
            for (int nfp = 0; nfp < 4; nfp++) {
                mma16816(acc[0][nfp * 2 + 0], a0, bb[nfp] + 0);
                mma16816(acc[0][nfp * 2 + 1], a0, bb[nfp] + 2);
                mma16816(acc[1][nfp * 2 + 0], a1, bb[nfp] + 0);
                mma16816(acc[1][nfp * 2 + 1], a1, bb[nfp] + 2);
            }
        }

        // ---- epilogue: ex2 sums + direct coalesced bf16 logit stores ----
        #pragma unroll
        for (int mf = 0; mf < 2; mf++)
            #pragma unroll
            for (int h = 0; h < 2; h++) {
                const int rl = wm * 32 + mf * 16 + h * 8 + qrow;
                const int rg = m0 + rl;
                float rsum = 0.f;
                #pragma unroll
                for (int sub = 0; sub < 2; sub++) {
                    uint32_t pk[4];
                    float t0 = 0.f, t1 = 0.f;
                    #pragma unroll
                    for (int jn = 0; jn < 4; jn++) {
                        const int j = sub * 4 + jn;
                        const int c = wn * 64 + j * 8 + (q << 1);
                        float x0 = acc[mf][j][h * 2 + 0] + bo_s[c];
                        float x1 = acc[mf][j][h * 2 + 1] + bo_s[c + 1];
                        t0 += ex2(x0);
                        t1 += ex2(x1);
                        __nv_bfloat162 pv = __floats2bfloat162_rn(x0, x1);
                        pk[jn] = *(uint32_t*)&pv;
                    }
                    rsum += t0 + t1;
                    const int gc = n0 + wn * 64 + sub * 32 + q * 8;
                    if (gc < V_)
                        __stcs((uint4*)(g_logits + (size_t)rg * V_ + gc),
                               make_uint4(pk[0], pk[1], pk[2], pk[3]));
                }
                rsum += __shfl_xor_sync(0xffffffffu, rsum, 1);
                rsum += __shfl_xor_sync(0xffffffffu, rsum, 2);
                if (q == 0) psum_base[rg] = rsum;   // 8 lanes -> 32B coalesced
            }

        if (it + 1 < MT_) {
            CP_WAIT0();      // next A tile (overlapped with mainloop+epilogue)
            __syncthreads(); // A-buffer swap -- the ONLY per-tile barrier
        }
    }
}

// ---- combine partials -> per-row LSE; pad cols contribute exactly PAD_ ----
__global__ void k_lse() {   // grid 32, block 256
    __shared__ float sm[4][64];
    const int tid = threadIdx.x;
    const int r = (blockIdx.x << 6) + (tid & 63);
    const int jl = tid >> 6;
    float S = 0.f;
    for (int k = jl; k < 2 * NT_; k += 4)
        S += g_psum[(size_t)k * B_ + r];
    sm[jl][tid & 63] = S;
    __syncthreads();
    if (tid < 64) {
        float s = sm[0][tid] + sm[1][tid] + sm[2][tid] + sm[3][tid] - PAD_;
        g_lse[(blockIdx.x << 6) + tid] = __logf(s);
    }
}

// ---- streaming fixup: out = scaled_logit * ln2 - lse[row] ----
// grid (13, B_), 256 thr; each thread 4 strided uint4 (8 bf16 each).
__global__ void __launch_bounds__(256) k_fix(float* __restrict__ out) {
    const int row = blockIdx.y;
    const float l = g_lse[row];
    const uint4* src = (const uint4*)(g_logits + (size_t)row * V_);
    float4* dst = (float4*)(out + (size_t)row * V_);
    const int c0 = blockIdx.x * 1024 + threadIdx.x;
    #pragma unroll
    for (int k = 0; k < 4; k++) {
        const int chunk = c0 + k * 256;
        if (chunk < V_ / 8) {
            const uint4 v = __ldcs(src + chunk);
            const __nv_bfloat162* bp = (const __nv_bfloat162*)&v;
            float4 o0, o1;
            float2 f;
            f = __bfloat1622float2(bp[0]); o0.x = fmaf(f.x, LN2_, -l); o0.y = fmaf(f.y, LN2_, -l);
            f = __bfloat1622float2(bp[1]); o0.z = fmaf(f.x, LN2_, -l); o0.w = fmaf(f.y, LN2_, -l);
            f = __bfloat1622float2(bp[2]); o1.x = fmaf(f.x, LN2_, -l); o1.y = fmaf(f.y, LN2_, -l);
            f = __bfloat1622float2(bp[3]); o1.z = fmaf(f.x, LN2_, -l); o1.w = fmaf(f.y, LN2_, -l);
            __stcs(dst + chunk * 2 + 0, o0);
            __stcs(dst + chunk * 2 + 1, o1);
        }
    }
}

extern "C" void kernel_launch(void* const* d_in, const int* in_sizes, int n_in,
                              void* d_out, int out_size) {
    const void*  cw = d_in[0];
    const float* Wc = (const float*)d_in[1];
    const float* bc = (const float*)d_in[2];
    const float* Wo = (const float*)d_in[3];
    const float* bo = (const float*)d_in[4];
    float* out = (float*)d_out;

    cudaFuncSetAttribute(k_gemm, cudaFuncAttributeMaxDynamicSharedMemorySize, SMEM_BYTES);

    k_detect<<<1, 256>>>(cw);
    k_gather<<<B_, 128>>>(cw, Wc, bc);
    k_cvt<<<((V_ * E_ / 4) + 255) / 256, 256>>>(Wo);
    k_gemm<<<NT_, 256, SMEM_BYTES>>>(bo);
    k_lse<<<32, 256>>>();
    k_fix<<<dim3(13, B_), 256>>>(out);
}

// round 14
// speedup vs baseline: 1.0153x; 1.0153x over previous
#include <cuda_runtime.h>
#include <cuda_bf16.h>
#include <math_constants.h>
#include <stdint.h>

#define B_  2048
#define E_  128
#define V_  100000
#define NT_ 782   // ceil(V/128)
#define MT_ 16    // B/128
#define PAD_ 96.0f   // NT_*128 - V_

#define LOG2E_ 1.4426950408889634f
#define LN2_   0.6931471805599453f

#define LDSA 136                     // smem row stride in bf16 (128 + 8 pad)
#define TILE_BYTES (128 * LDSA * 2)  // 34816 per tile buffer
#define SM_A0 0
#define SM_A1 TILE_BYTES
#define SM_B  (2 * TILE_BYTES)
#define SM_BO (3 * TILE_BYTES)             // 512 B bias (permuted, pre-scaled)
#define SMEM_BYTES (3 * TILE_BYTES + 512)  // 104960

// column permutation: c=(j2,j1,j0,q1,q0,e) -> g=(j2,q1,q0,j1,j0,e)
// makes each lane's 4 bf16x2 epilogue values 8 consecutive global columns.
#define PERM6(c) (((c) & 0x21) | (((c) & 0x06) << 2) | (((c) & 0x18) >> 2))

// ---- scratch (no allocation allowed; device globals) ----
__device__ __nv_bfloat16 g_embb[B_ * E_];            // emb * log2e, bf16
__device__ __nv_bfloat16 g_woutb[(size_t)V_ * E_];   // W_out bf16 (25.6 MB)
__device__ __nv_bfloat16 g_logits[(size_t)B_ * V_];  // bf16 scaled logits (logit*log2e)
__device__ float g_psum[(size_t)NT_ * 2 * B_];       // [ntile][wn][row] sumexp partials
__device__ float g_lse[B_];
__device__ int   g_is64;

// ================= helpers =================
__device__ __forceinline__ uint32_t smem_u32(const void* p) {
    uint32_t a;
    asm("{ .reg .u64 t; cvta.to.shared.u64 t, %1; cvt.u32.u64 %0, t; }" : "=r"(a) : "l"(p));
    return a;
}
__device__ __forceinline__ float ex2(float x) {
    float y;
    asm("ex2.approx.ftz.f32 %0, %1;" : "=f"(y) : "f"(x));
    return y;
}
__device__ __forceinline__ void cp16(uint32_t dst, const void* src) {
    asm volatile("cp.async.cg.shared.global [%0], [%1], 16;" :: "r"(dst), "l"(src));
}
__device__ __forceinline__ void cp16z(uint32_t dst, const void* src, int bytes) {
    asm volatile("cp.async.cg.shared.global [%0], [%1], 16, %2;"
                 :: "r"(dst), "l"(src), "r"(bytes));
}
#define CP_COMMIT() asm volatile("cp.async.commit_group;" ::: "memory")
#define CP_WAIT0()  asm volatile("cp.async.wait_group 0;" ::: "memory")

__device__ __forceinline__ void ldsm4(uint32_t* d, uint32_t a) {
    asm volatile("ldmatrix.sync.aligned.m8n8.x4.shared.b16 {%0,%1,%2,%3}, [%4];"
        : "=r"(d[0]), "=r"(d[1]), "=r"(d[2]), "=r"(d[3]) : "r"(a));
}
__device__ __forceinline__ void mma16816(float* c, const uint32_t* a, const uint32_t* b) {
    asm volatile("mma.sync.aligned.m16n8k16.row.col.f32.bf16.bf16.f32 "
        "{%0,%1,%2,%3}, {%4,%5,%6,%7}, {%8,%9}, {%0,%1,%2,%3};"
        : "+f"(c[0]), "+f"(c[1]), "+f"(c[2]), "+f"(c[3])
        : "r"(a[0]), "r"(a[1]), "r"(a[2]), "r"(a[3]), "r"(b[0]), "r"(b[1]));
}

// ---- dtype detection for center_word (jax int64 may actually be int32) ----
__global__ void k_detect(const void* __restrict__ cw) {
    __shared__ int ok;
    if (threadIdx.x == 0) ok = 1;
    __syncthreads();
    const int2* p = (const int2*)cw;
    int bad = 0;
    for (int i = threadIdx.x; i < 1024; i += 256) {
        int2 v = p[i];
        if (v.y != 0 || v.x < 0 || v.x >= V_) bad = 1;
    }
    if (bad) atomicAnd(&ok, 0);
    __syncthreads();
    if (threadIdx.x == 0) g_is64 = ok;
}

// emb scaled by log2e so the epilogue exp becomes a bare ex2
__global__ void k_gather(const void* __restrict__ cw,
                         const float* __restrict__ Wc,
                         const float* __restrict__ bc) {
    int b = blockIdx.x, e = threadIdx.x;
    long long idx;
    if (g_is64) idx = ((const long long*)cw)[b];
    else        idx = (long long)(((const int*)cw)[b]);
    float v = (Wc[(size_t)e * V_ + idx] + bc[e]) * LOG2E_;
    g_embb[b * E_ + e] = __float2bfloat16(v);
}

__global__ void k_cvt(const float* __restrict__ W) {
    size_t i = (size_t)blockIdx.x * blockDim.x + threadIdx.x;
    const size_t n4 = (size_t)V_ * E_ / 4;
    if (i >= n4) return;
    float4 f = ((const float4*)W)[i];
    __nv_bfloat162* o = (__nv_bfloat162*)g_woutb;
    o[2 * i + 0] = __floats2bfloat162_rn(f.x, f.y);
    o[2 * i + 1] = __floats2bfloat162_rn(f.z, f.w);
}

// ================= single GEMM pass =================
// One CTA per N-tile (128 cols of V), persistent over 16 M-tiles.
// 8 warps: 4(M) x 2(N); full warp tile 32M x 64N (acc[2][8][4]), 2 CTAs/SM.
// A double-buffered (prefetch before mainloop, wait after epilogue).
// B rows loaded PERMUTED (PERM6): direct STG.128 logit stores from registers.
// Row partials: 2 shuffles then 8 q==0 lanes store 32B coalesced straight to
// g_psum[ntile][wn][*] -- no smem funnel, ONE __syncthreads per M-tile (the
// A-buffer swap). Pad cols contribute ex2(0)=1; k_lse subtracts PAD_.
__global__ void __launch_bounds__(256, 2)
k_gemm(const float* __restrict__ b_out) {
    extern __shared__ __align__(1024) char smem[];
    const uint32_t sb = smem_u32(smem);
    float* bo_s = (float*)(smem + SM_BO);

    const int ntile = blockIdx.x;
    const int n0 = ntile * 128;
    const int tid = threadIdx.x, lane = tid & 31, wid = tid >> 5;
    const int wm = wid >> 1, wn = wid & 1;

    // permuted bias (pre-scaled by log2e); pad cols -> 0
    if (tid < 128) {
        int gcol = n0 + (tid & 64) + PERM6(tid & 63);
        bo_s[tid] = (gcol < V_) ? b_out[gcol] * LOG2E_ : 0.f;
    }

    // ---- B tile (once, permuted rows) + A tile 0 ----
    #pragma unroll
    for (int li = tid; li < 2048; li += 256) {
        int r = li >> 4, c = li & 15;
        int v = n0 + (r & 64) + PERM6(r & 63);
        cp16z(sb + SM_B + (uint32_t)r * (LDSA * 2) + c * 16,
              g_woutb + (size_t)(v < V_ ? v : 0) * E_ + c * 8, (v < V_) ? 16 : 0);
    }
    #pragma unroll
    for (int li = tid; li < 2048; li += 256) {
        int r = li >> 4, c = li & 15;
        cp16(sb + SM_A0 + (uint32_t)r * (LDSA * 2) + c * 16,
             g_embb + (size_t)r * E_ + c * 8);
    }
    CP_COMMIT();
    CP_WAIT0();
    __syncthreads();

    const uint32_t a_lane = (uint32_t)(wm * 32 + (lane & 15)) * (LDSA * 2)
                          + ((lane >> 4) << 3) * 2;
    const uint32_t b_rowb = sb + SM_B
                          + (uint32_t)(wn * 64 + (lane & 7) + ((lane >> 4) << 3)) * (LDSA * 2)
                          + (((lane >> 3) & 1) << 3) * 2;
    const int qrow = lane >> 2, q = lane & 3;
    float* psum_base = g_psum + ((size_t)ntile * 2 + wn) * B_;

    for (int it = 0; it < MT_; it++) {
        const int m0 = it * 128;
        const uint32_t a_base = sb + ((it & 1) ? SM_A1 : SM_A0) + a_lane;

        // prefetch next A tile into the other buffer (hidden under mainloop)
        if (it + 1 < MT_) {
            const uint32_t nb = sb + ((it & 1) ? SM_A0 : SM_A1);
            #pragma unroll
            for (int li = tid; li < 2048; li += 256) {
                int r = li >> 4, c = li & 15;
                cp16(nb + (uint32_t)r * (LDSA * 2) + c * 16,
                     g_embb + (size_t)(m0 + 128 + r) * E_ + c * 8);
            }
        }
        CP_COMMIT();

        // ---- mainloop: 128x128x128, full 32Mx64N warp tile ----
        float acc[2][8][4];
        #pragma unroll
        for (int i = 0; i < 2; i++)
            #pragma unroll
            for (int j = 0; j < 8; j++)
                #pragma unroll
                for (int k = 0; k < 4; k++) acc[i][j][k] = 0.f;

        #pragma unroll
        for (int ks = 0; ks < 8; ks++) {
            const uint32_t koff = (uint32_t)(ks * 16) * 2;
            uint32_t a0[4], a1[4], bb[4][4];
            ldsm4(a0, a_base + koff);
            ldsm4(a1, a_base + 16 * (LDSA * 2) + koff);
            #pragma unroll
            for (int nfp = 0; nfp < 4; nfp++)
                ldsm4(bb[nfp], b_rowb + (uint32_t)(nfp * 16) * (LDSA * 2) + koff);
            #pragma unroll
            for (int nfp = 0; nfp < 4; nfp++) {
                mma16816(acc[0][nfp * 2 + 0], a0, bb[nfp] + 0);
                mma16816(acc[0][nfp * 2 + 1], a0, bb[nfp] + 2);
                mma16816(acc[1][nfp * 2 + 0], a1, bb[nfp] + 0);
                mma16816(acc[1][nfp * 2 + 1], a1, bb[nfp] + 2);
            }
        }

        // ---- epilogue: ex2 sums + direct coalesced bf16 logit stores ----
        #pragma unroll
        for (int mf = 0; mf < 2; mf++)
            #pragma unroll
            for (int h = 0; h < 2; h++) {
                const int rl = wm * 32 + mf * 16 + h * 8 + qrow;
                const int rg = m0 + rl;
                float rsum = 0.f;
                #pragma unroll
                for (int sub = 0; sub < 2; sub++) {
                    uint32_t pk[4];
                    float t0 = 0.f, t1 = 0.f;
                    #pragma unroll
                    for (int jn = 0; jn < 4; jn++) {
                        const int j = sub * 4 + jn;
                        const int c = wn * 64 + j * 8 + (q << 1);
                        float x0 = acc[mf][j][h * 2 + 0] + bo_s[c];
                        float x1 = acc[mf][j][h * 2 + 1] + bo_s[c + 1];
                        t0 += ex2(x0);
                        t1 += ex2(x1);
                        __nv_bfloat162 pv = __floats2bfloat162_rn(x0, x1);
                        pk[jn] = *(uint32_t*)&pv;
                    }
                    rsum += t0 + t1;
                    const int gc = n0 + wn * 64 + sub * 32 + q * 8;
                    if (gc < V_)
                        __stcs((uint4*)(g_logits + (size_t)rg * V_ + gc),
                               make_uint4(pk[0], pk[1], pk[2], pk[3]));
                }
                rsum += __shfl_xor_sync(0xffffffffu, rsum, 1);
                rsum += __shfl_xor_sync(0xffffffffu, rsum, 2);
                if (q == 0) psum_base[rg] = rsum;   // 8 lanes -> 32B coalesced
            }

        if (it + 1 < MT_) {
            CP_WAIT0();      // next A tile (overlapped with mainloop+epilogue)
            __syncthreads(); // A-buffer swap -- the ONLY per-tile barrier
        }
    }
}

// ---- combine partials -> per-row LSE; pad cols contribute exactly PAD_ ----
__global__ void k_lse() {   // grid 32, block 256
    __shared__ float sm[4][64];
    const int tid = threadIdx.x;
    const int r = (blockIdx.x << 6) + (tid & 63);
    const int jl = tid >> 6;
    float S = 0.f;
    for (int k = jl; k < 2 * NT_; k += 4)
        S += g_psum[(size_t)k * B_ + r];
    sm[jl][tid & 63] = S;
    __syncthreads();
    if (tid < 64) {
        float s = sm[0][tid] + sm[1][tid] + sm[2][tid] + sm[3][tid] - PAD_;
        g_lse[(blockIdx.x << 6) + tid] = __logf(s);
    }
}

// ---- streaming fixup: out = scaled_logit * ln2 - lse[row] ----
// grid (49, B_); one uint4 (8 bf16) per thread -- R12 form (measured best).
__global__ void __launch_bounds__(256) k_fix(float* __restrict__ out) {
    const int row = blockIdx.y;
    const int chunk = blockIdx.x * 256 + threadIdx.x;   // uint4 index in row
    if (chunk >= V_ / 8) return;
    const float l = g_lse[row];
    const uint4 v = __ldcs((const uint4*)(g_logits + (size_t)row * V_) + chunk);
    const __nv_bfloat162* bp = (const __nv_bfloat162*)&v;
    float4 o0, o1;
    float2 f;
    f = __bfloat1622float2(bp[0]); o0.x = fmaf(f.x, LN2_, -l); o0.y = fmaf(f.y, LN2_, -l);
    f = __bfloat1622float2(bp[1]); o0.z = fmaf(f.x, LN2_, -l); o0.w = fmaf(f.y, LN2_, -l);
    f = __bfloat1622float2(bp[2]); o1.x = fmaf(f.x, LN2_, -l); o1.y = fmaf(f.y, LN2_, -l);
    f = __bfloat1622float2(bp[3]); o1.z = fmaf(f.x, LN2_, -l); o1.w = fmaf(f.y, LN2_, -l);
    float4* dst = (float4*)(out + (size_t)row * V_ + (size_t)chunk * 8);
    __stcs(dst + 0, o0);
    __stcs(dst + 1, o1);
}

extern "C" void kernel_launch(void* const* d_in, const int* in_sizes, int n_in,
                              void* d_out, int out_size) {
    const void*  cw = d_in[0];
    const float* Wc = (const float*)d_in[1];
    const float* bc = (const float*)d_in[2];
    const float* Wo = (const float*)d_in[3];
    const float* bo = (const float*)d_in[4];
    float* out = (float*)d_out;

    cudaFuncSetAttribute(k_gemm, cudaFuncAttributeMaxDynamicSharedMemorySize, SMEM_BYTES);

    k_detect<<<1, 256>>>(cw);
    k_gather<<<B_, 128>>>(cw, Wc, bc);
    k_cvt<<<((V_ * E_ / 4) + 255) / 256, 256>>>(Wo);
    k_gemm<<<NT_, 256, SMEM_BYTES>>>(bo);
    k_lse<<<32, 256>>>();
    k_fix<<<dim3((V_ / 8 + 255) / 256, B_), 256>>>(out);
}

// round 15
// speedup vs baseline: 1.0394x; 1.0238x over previous
#include <cuda_runtime.h>
#include <cuda_bf16.h>
#include <math_constants.h>
#include <stdint.h>

#define B_  2048
#define E_  128
#define V_  100000
#define NT_ 782   // ceil(V/128)
#define MT_ 16    // B/128
#define PAD_ 96.0f   // NT_*128 - V_

#define LOG2E_ 1.4426950408889634f
#define LN2_   0.6931471805599453f

#define LDSA 136                     // smem row stride in bf16 (128 + 8 pad)
#define TILE_BYTES (128 * LDSA * 2)  // 34816 per tile buffer
#define SM_A0 0
#define SM_A1 TILE_BYTES
#define SM_B  (2 * TILE_BYTES)
#define SM_BO (3 * TILE_BYTES)             // 512 B bias (permuted, pre-scaled)
#define SMEM_BYTES (3 * TILE_BYTES + 512)  // 104960

// column permutation: c=(j2,j1,j0,q1,q0,e) -> g=(j2,q1,q0,j1,j0,e)
// makes each lane's 4 bf16x2 epilogue values 8 consecutive global columns.
#define PERM6(c) (((c) & 0x21) | (((c) & 0x06) << 2) | (((c) & 0x18) >> 2))

// ---- scratch (no allocation allowed; device globals) ----
__device__ __nv_bfloat16 g_embb[B_ * E_];            // emb * log2e, bf16
__device__ __nv_bfloat16 g_logits[(size_t)B_ * V_];  // bf16 scaled logits (logit*log2e)
__device__ float g_psum[(size_t)NT_ * 2 * B_];       // [ntile][wn][row] sumexp partials
__device__ float g_lse[B_];
__device__ int   g_is64;

// ================= helpers =================
__device__ __forceinline__ uint32_t smem_u32(const void* p) {
    uint32_t a;
    asm("{ .reg .u64 t; cvta.to.shared.u64 t, %1; cvt.u32.u64 %0, t; }" : "=r"(a) : "l"(p));
    return a;
}
__device__ __forceinline__ float ex2(float x) {
    float y;
    asm("ex2.approx.ftz.f32 %0, %1;" : "=f"(y) : "f"(x));
    return y;
}
__device__ __forceinline__ void cp16(uint32_t dst, const void* src) {
    asm volatile("cp.async.cg.shared.global [%0], [%1], 16;" :: "r"(dst), "l"(src));
}
#define CP_COMMIT() asm volatile("cp.async.commit_group;" ::: "memory")
#define CP_WAIT0()  asm volatile("cp.async.wait_group 0;" ::: "memory")

__device__ __forceinline__ void ldsm4(uint32_t* d, uint32_t a) {
    asm volatile("ldmatrix.sync.aligned.m8n8.x4.shared.b16 {%0,%1,%2,%3}, [%4];"
        : "=r"(d[0]), "=r"(d[1]), "=r"(d[2]), "=r"(d[3]) : "r"(a));
}
__device__ __forceinline__ void mma16816(float* c, const uint32_t* a, const uint32_t* b) {
    asm volatile("mma.sync.aligned.m16n8k16.row.col.f32.bf16.bf16.f32 "
        "{%0,%1,%2,%3}, {%4,%5,%6,%7}, {%8,%9}, {%0,%1,%2,%3};"
        : "+f"(c[0]), "+f"(c[1]), "+f"(c[2]), "+f"(c[3])
        : "r"(a[0]), "r"(a[1]), "r"(a[2]), "r"(a[3]), "r"(b[0]), "r"(b[1]));
}

// ---- dtype detection for center_word (jax int64 may actually be int32) ----
__global__ void k_detect(const void* __restrict__ cw) {
    __shared__ int ok;
    if (threadIdx.x == 0) ok = 1;
    __syncthreads();
    const int2* p = (const int2*)cw;
    int bad = 0;
    for (int i = threadIdx.x; i < 1024; i += 256) {
        int2 v = p[i];
        if (v.y != 0 || v.x < 0 || v.x >= V_) bad = 1;
    }
    if (bad) atomicAnd(&ok, 0);
    __syncthreads();
    if (threadIdx.x == 0) g_is64 = ok;
}

// emb scaled by log2e so the epilogue exp becomes a bare ex2
__global__ void k_gather(const void* __restrict__ cw,
                         const float* __restrict__ Wc,
                         const float* __restrict__ bc) {
    int b = blockIdx.x, e = threadIdx.x;
    long long idx;
    if (g_is64) idx = ((const long long*)cw)[b];
    else        idx = (long long)(((const int*)cw)[b]);
    float v = (Wc[(size_t)e * V_ + idx] + bc[e]) * LOG2E_;
    g_embb[b * E_ + e] = __float2bfloat16(v);
}

// ================= single GEMM pass =================
// One CTA per N-tile (128 cols of V), persistent over 16 M-tiles.
// 8 warps: 4(M) x 2(N); full warp tile 32M x 64N (acc[2][8][4]), 2 CTAs/SM.
// B tile converted INLINE from W_out fp32 (LDG.128 x2 -> cvt -> STS.128,
// permuted rows via PERM6) -- no separate k_cvt kernel, W_out read once.
// A double-buffered via cp.async. Direct STG.128 logit stores (plain st so
// the tail stays L2-warm for k_fix). Row partials: 2 shuffles + q==0 lanes
// store 32B coalesced to g_psum[ntile][wn][*]; ONE __syncthreads per M-tile.
// Pad cols contribute ex2(0)=1; k_lse subtracts PAD_.
__global__ void __launch_bounds__(256, 2)
k_gemm(const float* __restrict__ b_out, const float* __restrict__ Wo) {
    extern __shared__ __align__(1024) char smem[];
    const uint32_t sb = smem_u32(smem);
    float* bo_s = (float*)(smem + SM_BO);

    const int ntile = blockIdx.x;
    const int n0 = ntile * 128;
    const int tid = threadIdx.x, lane = tid & 31, wid = tid >> 5;
    const int wm = wid >> 1, wn = wid & 1;

    // permuted bias (pre-scaled by log2e); pad cols -> 0
    if (tid < 128) {
        int gcol = n0 + (tid & 64) + PERM6(tid & 63);
        bo_s[tid] = (gcol < V_) ? b_out[gcol] * LOG2E_ : 0.f;
    }

    // ---- A tile 0 via cp.async (issued first; overlaps B conversion) ----
    #pragma unroll
    for (int li = tid; li < 2048; li += 256) {
        int r = li >> 4, c = li & 15;
        cp16(sb + SM_A0 + (uint32_t)r * (LDSA * 2) + c * 16,
             g_embb + (size_t)r * E_ + c * 8);
    }
    CP_COMMIT();

    // ---- B tile: load W_out fp32, convert to bf16, permuted rows ----
    #pragma unroll
    for (int li = tid; li < 2048; li += 256) {
        int r = li >> 4, c = li & 15;        // row, 16B-bf16 chunk (8 cols)
        int v = n0 + (r & 64) + PERM6(r & 63);
        uint4 pk = make_uint4(0, 0, 0, 0);
        if (v < V_) {
            const float4* src = (const float4*)(Wo + (size_t)v * E_ + c * 8);
            float4 f0 = __ldcs(src);
            float4 f1 = __ldcs(src + 1);
            __nv_bfloat162 h0 = __floats2bfloat162_rn(f0.x, f0.y);
            __nv_bfloat162 h1 = __floats2bfloat162_rn(f0.z, f0.w);
            __nv_bfloat162 h2 = __floats2bfloat162_rn(f1.x, f1.y);
            __nv_bfloat162 h3 = __floats2bfloat162_rn(f1.z, f1.w);
            pk = make_uint4(*(uint32_t*)&h0, *(uint32_t*)&h1,
                            *(uint32_t*)&h2, *(uint32_t*)&h3);
        }
        *(uint4*)(smem + SM_B + (uint32_t)r * (LDSA * 2) + c * 16) = pk;
    }
    CP_WAIT0();
    __syncthreads();

    const uint32_t a_lane = (uint32_t)(wm * 32 + (lane & 15)) * (LDSA * 2)
                          + ((lane >> 4) << 3) * 2;
    const uint32_t b_rowb = sb + SM_B
                          + (uint32_t)(wn * 64 + (lane & 7) + ((lane >> 4) << 3)) * (LDSA * 2)
                          + (((lane >> 3) & 1) << 3) * 2;
    const int qrow = lane >> 2, q = lane & 3;
    float* psum_base = g_psum + ((size_t)ntile * 2 + wn) * B_;

    for (int it = 0; it < MT_; it++) {
        const int m0 = it * 128;
        const uint32_t a_base = sb + ((it & 1) ? SM_A1 : SM_A0) + a_lane;

        // prefetch next A tile into the other buffer (hidden under mainloop)
        if (it + 1 < MT_) {
            const uint32_t nb = sb + ((it & 1) ? SM_A0 : SM_A1);
            #pragma unroll
            for (int li = tid; li < 2048; li += 256) {
                int r = li >> 4, c = li & 15;
                cp16(nb + (uint32_t)r * (LDSA * 2) + c * 16,
                     g_embb + (size_t)(m0 + 128 + r) * E_ + c * 8);
            }
        }
        CP_COMMIT();

        // ---- mainloop: 128x128x128, full 32Mx64N warp tile ----
        float acc[2][8][4];
        #pragma unroll
        for (int i = 0; i < 2; i++)
            #pragma unroll
            for (int j = 0; j < 8; j++)
                #pragma unroll
                for (int k = 0; k < 4; k++) acc[i][j][k] = 0.f;

        #pragma unroll
        for (int ks = 0; ks < 8; ks++) {
            const uint32_t koff = (uint32_t)(ks * 16) * 2;
            uint32_t a0[4], a1[4], bb[4][4];
            ldsm4(a0, a_base + koff);
            ldsm4(a1, a_base + 16 * (LDSA * 2) + koff);
            #pragma unroll
            for (int nfp = 0; nfp < 4; nfp++)
                ldsm4(bb[nfp], b_rowb + (uint32_t)(nfp * 16) * (LDSA * 2) + koff);
            #pragma unroll
            for (int nfp = 0; nfp < 4; nfp++) {
                mma16816(acc[0][nfp * 2 + 0], a0, bb[nfp] + 0);
                mma16816(acc[0][nfp * 2 + 1], a0, bb[nfp] + 2);
                mma16816(acc[1][nfp * 2 + 0], a1, bb[nfp] + 0);
                mma16816(acc[1][nfp * 2 + 1], a1, bb[nfp] + 2);
            }
        }

        // ---- epilogue: ex2 sums + direct coalesced bf16 logit stores ----
        #pragma unroll
        for (int mf = 0; mf < 2; mf++)
            #pragma unroll
            for (int h = 0; h < 2; h++) {
                const int rl = wm * 32 + mf * 16 + h * 8 + qrow;
                const int rg = m0 + rl;
                float rsum = 0.f;
                #pragma unroll
                for (int sub = 0; sub < 2; sub++) {
                    uint32_t pk[4];
                    float t0 = 0.f, t1 = 0.f;
                    #pragma unroll
                    for (int jn = 0; jn < 4; jn++) {
                        const int j = sub * 4 + jn;
                        const int c = wn * 64 + j * 8 + (q << 1);
                        float x0 = acc[mf][j][h * 2 + 0] + bo_s[c];
                        float x1 = acc[mf][j][h * 2 + 1] + bo_s[c + 1];
                        t0 += ex2(x0);
                        t1 += ex2(x1);
                        __nv_bfloat162 pv = __floats2bfloat162_rn(x0, x1);
                        pk[jn] = *(uint32_t*)&pv;
                    }
                    rsum += t0 + t1;
                    const int gc = n0 + wn * 64 + sub * 32 + q * 8;
                    if (gc < V_)      // plain store: keep L2-warm for k_fix
                        *(uint4*)(g_logits + (size_t)rg * V_ + gc) =
                            make_uint4(pk[0], pk[1], pk[2], pk[3]);
                }
                rsum += __shfl_xor_sync(0xffffffffu, rsum, 1);
                rsum += __shfl_xor_sync(0xffffffffu, rsum, 2);
                if (q == 0) psum_base[rg] = rsum;   // 8 lanes -> 32B coalesced
            }

        if (it + 1 < MT_) {
            CP_WAIT0();      // next A tile (overlapped with mainloop+epilogue)
            __syncthreads(); // A-buffer swap -- the ONLY per-tile barrier
        }
    }
}

// ---- combine partials -> per-row LSE; pad cols contribute exactly PAD_ ----
__global__ void k_lse() {   // grid 32, block 256
    __shared__ float sm[4][64];
    const int tid = threadIdx.x;
    const int r = (blockIdx.x << 6) + (tid & 63);
    const int jl = tid >> 6;
    float S = 0.f;
    for (int k = jl; k < 2 * NT_; k += 4)
        S += g_psum[(size_t)k * B_ + r];
    sm[jl][tid & 63] = S;
    __syncthreads();
    if (tid < 64) {
        float s = sm[0][tid] + sm[1][tid] + sm[2][tid] + sm[3][tid] - PAD_;
        g_lse[(blockIdx.x << 6) + tid] = __logf(s);
    }
}

// ---- streaming fixup: out = scaled_logit * ln2 - lse[row] ----
// grid (49, B_); one uint4 per thread. Rows processed DESCENDING so the
// L2-warm tail of g_logits (last-written rows) is read before eviction.
__global__ void __launch_bounds__(256) k_fix(float* __restrict__ out) {
    const int row = (B_ - 1) - blockIdx.y;
    const int chunk = blockIdx.x * 256 + threadIdx.x;   // uint4 index in row
    if (chunk >= V_ / 8) return;
    const float l = g_lse[row];
    const uint4 v = __ldcs((const uint4*)(g_logits + (size_t)row * V_) + chunk);
    const __nv_bfloat162* bp = (const __nv_bfloat162*)&v;
    float4 o0, o1;
    float2 f;
    f = __bfloat1622float2(bp[0]); o0.x = fmaf(f.x, LN2_, -l); o0.y = fmaf(f.y, LN2_, -l);
    f = __bfloat1622float2(bp[1]); o0.z = fmaf(f.x, LN2_, -l); o0.w = fmaf(f.y, LN2_, -l);
    f = __bfloat1622float2(bp[2]); o1.x = fmaf(f.x, LN2_, -l); o1.y = fmaf(f.y, LN2_, -l);
    f = __bfloat1622float2(bp[3]); o1.z = fmaf(f.x, LN2_, -l); o1.w = fmaf(f.y, LN2_, -l);
    float4* dst = (float4*)(out + (size_t)row * V_ + (size_t)chunk * 8);
    __stcs(dst + 0, o0);
    __stcs(dst + 1, o1);
}

extern "C" void kernel_launch(void* const* d_in, const int* in_sizes, int n_in,
                              void* d_out, int out_size) {
    const void*  cw = d_in[0];
    const float* Wc = (const float*)d_in[1];
    const float* bc = (const float*)d_in[2];
    const float* Wo = (const float*)d_in[3];
    const float* bo = (const float*)d_in[4];
    float* out = (float*)d_out;

    cudaFuncSetAttribute(k_gemm, cudaFuncAttributeMaxDynamicSharedMemorySize, SMEM_BYTES);

    k_detect<<<1, 256>>>(cw);
    k_gather<<<B_, 128>>>(cw, Wc, bc);
    k_gemm<<<NT_, 256, SMEM_BYTES>>>(bo, Wo);
    k_lse<<<32, 256>>>();
    k_fix<<<dim3((V_ / 8 + 255) / 256, B_), 256>>>(out);
}

// round 16
// speedup vs baseline: 1.0679x; 1.0274x over previous
#include <cuda_runtime.h>
#include <cuda_bf16.h>
#include <math_constants.h>
#include <stdint.h>

#define B_  2048
#define E_  128
#define V_  100000
#define NT_ 782   // ceil(V/128)
#define MT_ 16    // B/128
#define PAD_ 96.0f   // NT_*128 - V_

#define LOG2E_ 1.4426950408889634f
#define LN2_   0.6931471805599453f

#define LDSA 136                     // smem row stride in bf16 (128 + 8 pad)
#define TILE_BYTES (128 * LDSA * 2)  // 34816 per tile buffer
#define SM_A0 0
#define SM_A1 TILE_BYTES
#define SM_B  (2 * TILE_BYTES)
#define SM_BO (3 * TILE_BYTES)             // 512 B bias (permuted, pre-scaled)
#define SMEM_BYTES (3 * TILE_BYTES + 512)  // 104960

// column permutation: c=(j2,j1,j0,q1,q0,e) -> g=(j2,q1,q0,j1,j0,e)
// makes each lane's 4 bf16x2 epilogue values 8 consecutive global columns.
#define PERM6(c) (((c) & 0x21) | (((c) & 0x06) << 2) | (((c) & 0x18) >> 2))

// ---- scratch (no allocation allowed; device globals) ----
__device__ __nv_bfloat16 g_embb[B_ * E_];            // emb * log2e, bf16
__device__ __nv_bfloat16 g_logits[(size_t)B_ * V_];  // bf16 scaled logits (logit*log2e)
__device__ float g_psum[(size_t)NT_ * 2 * B_];       // [ntile][wn][row] sumexp partials
__device__ float g_ps2[8 * B_];                      // [kslice][row] stage-1 partials
__device__ float g_lse[B_];
__device__ int   g_is64;

// ================= helpers =================
__device__ __forceinline__ uint32_t smem_u32(const void* p) {
    uint32_t a;
    asm("{ .reg .u64 t; cvta.to.shared.u64 t, %1; cvt.u32.u64 %0, t; }" : "=r"(a) : "l"(p));
    return a;
}
__device__ __forceinline__ float ex2(float x) {
    float y;
    asm("ex2.approx.ftz.f32 %0, %1;" : "=f"(y) : "f"(x));
    return y;
}
__device__ __forceinline__ void cp16(uint32_t dst, const void* src) {
    asm volatile("cp.async.cg.shared.global [%0], [%1], 16;" :: "r"(dst), "l"(src));
}
#define CP_COMMIT() asm volatile("cp.async.commit_group;" ::: "memory")
#define CP_WAIT0()  asm volatile("cp.async.wait_group 0;" ::: "memory")

__device__ __forceinline__ void ldsm4(uint32_t* d, uint32_t a) {
    asm volatile("ldmatrix.sync.aligned.m8n8.x4.shared.b16 {%0,%1,%2,%3}, [%4];"
        : "=r"(d[0]), "=r"(d[1]), "=r"(d[2]), "=r"(d[3]) : "r"(a));
}
__device__ __forceinline__ void mma16816(float* c, const uint32_t* a, const uint32_t* b) {
    asm volatile("mma.sync.aligned.m16n8k16.row.col.f32.bf16.bf16.f32 "
        "{%0,%1,%2,%3}, {%4,%5,%6,%7}, {%8,%9}, {%0,%1,%2,%3};"
        : "+f"(c[0]), "+f"(c[1]), "+f"(c[2]), "+f"(c[3])
        : "r"(a[0]), "r"(a[1]), "r"(a[2]), "r"(a[3]), "r"(b[0]), "r"(b[1]));
}

// ---- dtype detection for center_word (jax int64 may actually be int32) ----
__global__ void k_detect(const void* __restrict__ cw) {
    __shared__ int ok;
    if (threadIdx.x == 0) ok = 1;
    __syncthreads();
    const int2* p = (const int2*)cw;
    int bad = 0;
    for (int i = threadIdx.x; i < 1024; i += 256) {
        int2 v = p[i];
        if (v.y != 0 || v.x < 0 || v.x >= V_) bad = 1;
    }
    if (bad) atomicAnd(&ok, 0);
    __syncthreads();
    if (threadIdx.x == 0) g_is64 = ok;
}

// emb scaled by log2e so the epilogue exp becomes a bare ex2
__global__ void k_gather(const void* __restrict__ cw,
                         const float* __restrict__ Wc,
                         const float* __restrict__ bc) {
    int b = blockIdx.x, e = threadIdx.x;
    long long idx;
    if (g_is64) idx = ((const long long*)cw)[b];
    else        idx = (long long)(((const int*)cw)[b]);
    float v = (Wc[(size_t)e * V_ + idx] + bc[e]) * LOG2E_;
    g_embb[b * E_ + e] = __float2bfloat16(v);
}

// ================= single GEMM pass =================
// One CTA per N-tile (128 cols of V), persistent over 16 M-tiles.
// 8 warps: 4(M) x 2(N); full warp tile 32M x 64N (acc[2][8][4]), 2 CTAs/SM.
// B tile converted INLINE from W_out fp32; A double-buffered via cp.async.
// Direct STG.128 logit stores (plain st: tail stays L2-warm for k_fix).
// Row partials via 2 shuffles + q==0 coalesced 32B stores; ONE barrier/tile.
// Pad cols contribute ex2(0)=1; k_lse subtracts PAD_.
__global__ void __launch_bounds__(256, 2)
k_gemm(const float* __restrict__ b_out, const float* __restrict__ Wo) {
    extern __shared__ __align__(1024) char smem[];
    const uint32_t sb = smem_u32(smem);
    float* bo_s = (float*)(smem + SM_BO);

    const int ntile = blockIdx.x;
    const int n0 = ntile * 128;
    const int tid = threadIdx.x, lane = tid & 31, wid = tid >> 5;
    const int wm = wid >> 1, wn = wid & 1;

    // permuted bias (pre-scaled by log2e); pad cols -> 0
    if (tid < 128) {
        int gcol = n0 + (tid & 64) + PERM6(tid & 63);
        bo_s[tid] = (gcol < V_) ? b_out[gcol] * LOG2E_ : 0.f;
    }

    // ---- A tile 0 via cp.async (issued first; overlaps B conversion) ----
    #pragma unroll
    for (int li = tid; li < 2048; li += 256) {
        int r = li >> 4, c = li & 15;
        cp16(sb + SM_A0 + (uint32_t)r * (LDSA * 2) + c * 16,
             g_embb + (size_t)r * E_ + c * 8);
    }
    CP_COMMIT();

    // ---- B tile: load W_out fp32, convert to bf16, permuted rows ----
    #pragma unroll
    for (int li = tid; li < 2048; li += 256) {
        int r = li >> 4, c = li & 15;        // row, 16B-bf16 chunk (8 cols)
        int v = n0 + (r & 64) + PERM6(r & 63);
        uint4 pk = make_uint4(0, 0, 0, 0);
        if (v < V_) {
            const float4* src = (const float4*)(Wo + (size_t)v * E_ + c * 8);
            float4 f0 = __ldcs(src);
            float4 f1 = __ldcs(src + 1);
            __nv_bfloat162 h0 = __floats2bfloat162_rn(f0.x, f0.y);
            __nv_bfloat162 h1 = __floats2bfloat162_rn(f0.z, f0.w);
            __nv_bfloat162 h2 = __floats2bfloat162_rn(f1.x, f1.y);
            __nv_bfloat162 h3 = __floats2bfloat162_rn(f1.z, f1.w);
            pk = make_uint4(*(uint32_t*)&h0, *(uint32_t*)&h1,
                            *(uint32_t*)&h2, *(uint32_t*)&h3);
        }
        *(uint4*)(smem + SM_B + (uint32_t)r * (LDSA * 2) + c * 16) = pk;
    }
    CP_WAIT0();
    __syncthreads();

    const uint32_t a_lane = (uint32_t)(wm * 32 + (lane & 15)) * (LDSA * 2)
                          + ((lane >> 4) << 3) * 2;
    const uint32_t b_rowb = sb + SM_B
                          + (uint32_t)(wn * 64 + (lane & 7) + ((lane >> 4) << 3)) * (LDSA * 2)
                          + (((lane >> 3) & 1) << 3) * 2;
    const int qrow = lane >> 2, q = lane & 3;
    float* psum_base = g_psum + ((size_t)ntile * 2 + wn) * B_;

    for (int it = 0; it < MT_; it++) {
        const int m0 = it * 128;
        const uint32_t a_base = sb + ((it & 1) ? SM_A1 : SM_A0) + a_lane;

        // prefetch next A tile into the other buffer (hidden under mainloop)
        if (it + 1 < MT_) {
            const uint32_t nb = sb + ((it & 1) ? SM_A0 : SM_A1);
            #pragma unroll
            for (int li = tid; li < 2048; li += 256) {
                int r = li >> 4, c = li & 15;
                cp16(nb + (uint32_t)r * (LDSA * 2) + c * 16,
                     g_embb + (size_t)(m0 + 128 + r) * E_ + c * 8);
            }
        }
        CP_COMMIT();

        // ---- mainloop: 128x128x128, full 32Mx64N warp tile ----
        float acc[2][8][4];
        #pragma unroll
        for (int i = 0; i < 2; i++)
            #pragma unroll
            for (int j = 0; j < 8; j++)
                #pragma unroll
                for (int k = 0; k < 4; k++) acc[i][j][k] = 0.f;

        #pragma unroll
        for (int ks = 0; ks < 8; ks++) {
            const uint32_t koff = (uint32_t)(ks * 16) * 2;
            uint32_t a0[4], a1[4], bb[4][4];
            ldsm4(a0, a_base + koff);
            ldsm4(a1, a_base + 16 * (LDSA * 2) + koff);
            #pragma unroll
            for (int nfp = 0; nfp < 4; nfp++)
                ldsm4(bb[nfp], b_rowb + (uint32_t)(nfp * 16) * (LDSA * 2) + koff);
            #pragma unroll
            for (int nfp = 0; nfp < 4; nfp++) {
                mma16816(acc[0][nfp * 2 + 0], a0, bb[nfp] + 0);
                mma16816(acc[0][nfp * 2 + 1], a0, bb[nfp] + 2);
                mma16816(acc[1][nfp * 2 + 0], a1, bb[nfp] + 0);
                mma16816(acc[1][nfp * 2 + 1], a1, bb[nfp] + 2);
            }
        }

        // ---- epilogue: ex2 sums + direct coalesced bf16 logit stores ----
        #pragma unroll
        for (int mf = 0; mf < 2; mf++)
            #pragma unroll
            for (int h = 0; h < 2; h++) {
                const int rl = wm * 32 + mf * 16 + h * 8 + qrow;
                const int rg = m0 + rl;
                float rsum = 0.f;
                #pragma unroll
                for (int sub = 0; sub < 2; sub++) {
                    uint32_t pk[4];
                    float t0 = 0.f, t1 = 0.f;
                    #pragma unroll
                    for (int jn = 0; jn < 4; jn++) {
                        const int j = sub * 4 + jn;
                        const int c = wn * 64 + j * 8 + (q << 1);
                        float x0 = acc[mf][j][h * 2 + 0] + bo_s[c];
                        float x1 = acc[mf][j][h * 2 + 1] + bo_s[c + 1];
                        t0 += ex2(x0);
                        t1 += ex2(x1);
                        __nv_bfloat162 pv = __floats2bfloat162_rn(x0, x1);
                        pk[jn] = *(uint32_t*)&pv;
                    }
                    rsum += t0 + t1;
                    const int gc = n0 + wn * 64 + sub * 32 + q * 8;
                    if (gc < V_)      // plain store: keep L2-warm for k_fix
                        *(uint4*)(g_logits + (size_t)rg * V_ + gc) =
                            make_uint4(pk[0], pk[1], pk[2], pk[3]);
                }
                rsum += __shfl_xor_sync(0xffffffffu, rsum, 1);
                rsum += __shfl_xor_sync(0xffffffffu, rsum, 2);
                if (q == 0) psum_base[rg] = rsum;   // 8 lanes -> 32B coalesced
            }

        if (it + 1 < MT_) {
            CP_WAIT0();      // next A tile (overlapped with mainloop+epilogue)
            __syncthreads(); // A-buffer swap -- the ONLY per-tile barrier
        }
    }
}

// ---- LSE stage 1: grid (8 kslices, 32 rowgroups), 256 thr ----
// thread (jl, row): sums k = kslice*4 + jl, step 32 over [0, 2*NT_),
// 4-deep unroll for MLP; 4-lane combine in smem -> g_ps2[kslice][row].
__global__ void k_lse1() {
    __shared__ float sm[4][64];
    const int tid = threadIdx.x;
    const int kslice = blockIdx.x;            // 0..7
    const int r = (blockIdx.y << 6) + (tid & 63);
    const int jl = tid >> 6;                  // 0..3
    const int k0 = kslice * 4 + jl;
    float s0 = 0.f, s1 = 0.f, s2 = 0.f, s3 = 0.f;
    int k = k0;
    for (; k + 96 < 2 * NT_; k += 128) {
        s0 += g_psum[(size_t)(k      ) * B_ + r];
        s1 += g_psum[(size_t)(k + 32 ) * B_ + r];
        s2 += g_psum[(size_t)(k + 64 ) * B_ + r];
        s3 += g_psum[(size_t)(k + 96 ) * B_ + r];
    }
    for (; k < 2 * NT_; k += 32)
        s0 += g_psum[(size_t)k * B_ + r];
    sm[jl][tid & 63] = (s0 + s1) + (s2 + s3);
    __syncthreads();
    if (tid < 64)
        g_ps2[kslice * B_ + (blockIdx.y << 6) + tid] =
            (sm[0][tid] + sm[1][tid]) + (sm[2][tid] + sm[3][tid]);
}

// ---- LSE stage 2: 8 blocks x 256 thr; combine 8 partials + log ----
__global__ void k_lse2() {
    const int r = blockIdx.x * 256 + threadIdx.x;
    float s = -PAD_;
    #pragma unroll
    for (int i = 0; i < 8; i++)
        s += g_ps2[i * B_ + r];
    g_lse[r] = __logf(s);
}

// ---- streaming fixup: out = scaled_logit * ln2 - lse[row] ----
// grid (49, B_); one uint4 per thread. Rows processed DESCENDING so the
// L2-warm tail of g_logits (last-written rows) is read before eviction.
__global__ void __launch_bounds__(256) k_fix(float* __restrict__ out) {
    const int row = (B_ - 1) - blockIdx.y;
    const int chunk = blockIdx.x * 256 + threadIdx.x;   // uint4 index in row
    if (chunk >= V_ / 8) return;
    const float l = g_lse[row];
    const uint4 v = __ldcs((const uint4*)(g_logits + (size_t)row * V_) + chunk);
    const __nv_bfloat162* bp = (const __nv_bfloat162*)&v;
    float4 o0, o1;
    float2 f;
    f = __bfloat1622float2(bp[0]); o0.x = fmaf(f.x, LN2_, -l); o0.y = fmaf(f.y, LN2_, -l);
    f = __bfloat1622float2(bp[1]); o0.z = fmaf(f.x, LN2_, -l); o0.w = fmaf(f.y, LN2_, -l);
    f = __bfloat1622float2(bp[2]); o1.x = fmaf(f.x, LN2_, -l); o1.y = fmaf(f.y, LN2_, -l);
    f = __bfloat1622float2(bp[3]); o1.z = fmaf(f.x, LN2_, -l); o1.w = fmaf(f.y, LN2_, -l);
    float4* dst = (float4*)(out + (size_t)row * V_ + (size_t)chunk * 8);
    __stcs(dst + 0, o0);
    __stcs(dst + 1, o1);
}

extern "C" void kernel_launch(void* const* d_in, const int* in_sizes, int n_in,
                              void* d_out, int out_size) {
    const void*  cw = d_in[0];
    const float* Wc = (const float*)d_in[1];
    const float* bc = (const float*)d_in[2];
    const float* Wo = (const float*)d_in[3];
    const float* bo = (const float*)d_in[4];
    float* out = (float*)d_out;

    cudaFuncSetAttribute(k_gemm, cudaFuncAttributeMaxDynamicSharedMemorySize, SMEM_BYTES);

    k_detect<<<1, 256>>>(cw);
    k_gather<<<B_, 128>>>(cw, Wc, bc);
    k_gemm<<<NT_, 256, SMEM_BYTES>>>(bo, Wo);
    k_lse1<<<dim3(8, 32), 256>>>();
    k_lse2<<<8, 256>>>();
    k_fix<<<dim3((V_ / 8 + 255) / 256, B_), 256>>>(out);
}

// round 17
// speedup vs baseline: 1.0994x; 1.0294x over previous
#include <cuda_runtime.h>
#include <cuda_bf16.h>
#include <math_constants.h>
#include <stdint.h>

#define B_  2048
#define E_  128
#define V_  100000
#define NT_ 782   // ceil(V/128)
#define MT_ 16    // B/128
#define PAD_ 96.0f   // NT_*128 - V_

#define LOG2E_ 1.4426950408889634f
#define LN2_   0.6931471805599453f

#define LDSA 136                     // smem row stride in bf16 (128 + 8 pad)
#define TILE_BYTES (128 * LDSA * 2)  // 34816 per tile buffer
#define SM_A0 0
#define SM_A1 TILE_BYTES
#define SM_B  (2 * TILE_BYTES)
#define SM_BO (3 * TILE_BYTES)             // 512 B bias (permuted, pre-scaled)
#define SMEM_BYTES (3 * TILE_BYTES + 512)  // 104960

// column permutation: c=(j2,j1,j0,q1,q0,e) -> g=(j2,q1,q0,j1,j0,e)
// makes each lane's 4 bf16x2 epilogue values 8 consecutive global columns.
#define PERM6(c) (((c) & 0x21) | (((c) & 0x06) << 2) | (((c) & 0x18) >> 2))

// ---- scratch (no allocation allowed; device globals) ----
__device__ __nv_bfloat16 g_embb[B_ * E_];            // emb * log2e, bf16
__device__ __nv_bfloat16 g_logits[(size_t)B_ * V_];  // bf16 scaled logits (logit*log2e)
__device__ float g_lsum[B_];                         // per-row sumexp (REDG target)
__device__ float g_lse[B_];
__device__ int   g_is64;

// ================= helpers =================
__device__ __forceinline__ uint32_t smem_u32(const void* p) {
    uint32_t a;
    asm("{ .reg .u64 t; cvta.to.shared.u64 t, %1; cvt.u32.u64 %0, t; }" : "=r"(a) : "l"(p));
    return a;
}
__device__ __forceinline__ float ex2(float x) {
    float y;
    asm("ex2.approx.ftz.f32 %0, %1;" : "=f"(y) : "f"(x));
    return y;
}
__device__ __forceinline__ void cp16(uint32_t dst, const void* src) {
    asm volatile("cp.async.cg.shared.global [%0], [%1], 16;" :: "r"(dst), "l"(src));
}
#define CP_COMMIT() asm volatile("cp.async.commit_group;" ::: "memory")
#define CP_WAIT0()  asm volatile("cp.async.wait_group 0;" ::: "memory")

__device__ __forceinline__ void ldsm4(uint32_t* d, uint32_t a) {
    asm volatile("ldmatrix.sync.aligned.m8n8.x4.shared.b16 {%0,%1,%2,%3}, [%4];"
        : "=r"(d[0]), "=r"(d[1]), "=r"(d[2]), "=r"(d[3]) : "r"(a));
}
__device__ __forceinline__ void mma16816(float* c, const uint32_t* a, const uint32_t* b) {
    asm volatile("mma.sync.aligned.m16n8k16.row.col.f32.bf16.bf16.f32 "
        "{%0,%1,%2,%3}, {%4,%5,%6,%7}, {%8,%9}, {%0,%1,%2,%3};"
        : "+f"(c[0]), "+f"(c[1]), "+f"(c[2]), "+f"(c[3])
        : "r"(a[0]), "r"(a[1]), "r"(a[2]), "r"(a[3]), "r"(b[0]), "r"(b[1]));
}

// ---- zero the REDG accumulator (must re-run every launch: deterministic) ----
__global__ void k_zero() { g_lsum[blockIdx.x * 256 + threadIdx.x] = 0.f; }

// ---- dtype detection for center_word (jax int64 may actually be int32) ----
__global__ void k_detect(const void* __restrict__ cw) {
    __shared__ int ok;
    if (threadIdx.x == 0) ok = 1;
    __syncthreads();
    const int2* p = (const int2*)cw;
    int bad = 0;
    for (int i = threadIdx.x; i < 1024; i += 256) {
        int2 v = p[i];
        if (v.y != 0 || v.x < 0 || v.x >= V_) bad = 1;
    }
    if (bad) atomicAnd(&ok, 0);
    __syncthreads();
    if (threadIdx.x == 0) g_is64 = ok;
}

// emb scaled by log2e so the epilogue exp becomes a bare ex2
__global__ void k_gather(const void* __restrict__ cw,
                         const float* __restrict__ Wc,
                         const float* __restrict__ bc) {
    int b = blockIdx.x, e = threadIdx.x;
    long long idx;
    if (g_is64) idx = ((const long long*)cw)[b];
    else        idx = (long long)(((const int*)cw)[b]);
    float v = (Wc[(size_t)e * V_ + idx] + bc[e]) * LOG2E_;
    g_embb[b * E_ + e] = __float2bfloat16(v);
}

// ================= single GEMM pass =================
// One CTA per N-tile (128 cols of V), persistent over 16 M-tiles.
// 8 warps: 4(M) x 2(N); full warp tile 32M x 64N (acc[2][8][4]), 2 CTAs/SM.
// B tile converted INLINE from W_out fp32; A double-buffered via cp.async.
// Direct STG.128 logit stores (plain st: tail stays L2-warm for k_fix).
// Row sums go STRAIGHT to g_lsum via red.global.add.f32 from q==0 lanes:
// no psum scratch, no reduction kernel. ONE __syncthreads per M-tile.
// Pad cols contribute ex2(0)=1; k_lse2 subtracts PAD_.
__global__ void __launch_bounds__(256, 2)
k_gemm(const float* __restrict__ b_out, const float* __restrict__ Wo) {
    extern __shared__ __align__(1024) char smem[];
    const uint32_t sb = smem_u32(smem);
    float* bo_s = (float*)(smem + SM_BO);

    const int ntile = blockIdx.x;
    const int n0 = ntile * 128;
    const int tid = threadIdx.x, lane = tid & 31, wid = tid >> 5;
    const int wm = wid >> 1, wn = wid & 1;

    // permuted bias (pre-scaled by log2e); pad cols -> 0
    if (tid < 128) {
        int gcol = n0 + (tid & 64) + PERM6(tid & 63);
        bo_s[tid] = (gcol < V_) ? b_out[gcol] * LOG2E_ : 0.f;
    }

    // ---- A tile 0 via cp.async (issued first; overlaps B conversion) ----
    #pragma unroll
    for (int li = tid; li < 2048; li += 256) {
        int r = li >> 4, c = li & 15;
        cp16(sb + SM_A0 + (uint32_t)r * (LDSA * 2) + c * 16,
             g_embb + (size_t)r * E_ + c * 8);
    }
    CP_COMMIT();

    // ---- B tile: load W_out fp32, convert to bf16, permuted rows ----
    #pragma unroll
    for (int li = tid; li < 2048; li += 256) {
        int r = li >> 4, c = li & 15;        // row, 16B-bf16 chunk (8 cols)
        int v = n0 + (r & 64) + PERM6(r & 63);
        uint4 pk = make_uint4(0, 0, 0, 0);
        if (v < V_) {
            const float4* src = (const float4*)(Wo + (size_t)v * E_ + c * 8);
            float4 f0 = __ldcs(src);
            float4 f1 = __ldcs(src + 1);
            __nv_bfloat162 h0 = __floats2bfloat162_rn(f0.x, f0.y);
            __nv_bfloat162 h1 = __floats2bfloat162_rn(f0.z, f0.w);
            __nv_bfloat162 h2 = __floats2bfloat162_rn(f1.x, f1.y);
            __nv_bfloat162 h3 = __floats2bfloat162_rn(f1.z, f1.w);
            pk = make_uint4(*(uint32_t*)&h0, *(uint32_t*)&h1,
                            *(uint32_t*)&h2, *(uint32_t*)&h3);
        }
        *(uint4*)(smem + SM_B + (uint32_t)r * (LDSA * 2) + c * 16) = pk;
    }
    CP_WAIT0();
    __syncthreads();

    const uint32_t a_lane = (uint32_t)(wm * 32 + (lane & 15)) * (LDSA * 2)
                          + ((lane >> 4) << 3) * 2;
    const uint32_t b_rowb = sb + SM_B
                          + (uint32_t)(wn * 64 + (lane & 7) + ((lane >> 4) << 3)) * (LDSA * 2)
                          + (((lane >> 3) & 1) << 3) * 2;
    const int qrow = lane >> 2, q = lane & 3;

    for (int it = 0; it < MT_; it++) {
        const int m0 = it * 128;
        const uint32_t a_base = sb + ((it & 1) ? SM_A1 : SM_A0) + a_lane;

        // prefetch next A tile into the other buffer (hidden under mainloop)
        if (it + 1 < MT_) {
            const uint32_t nb = sb + ((it & 1) ? SM_A0 : SM_A1);
            #pragma unroll
            for (int li = tid; li < 2048; li += 256) {
                int r = li >> 4, c = li & 15;
                cp16(nb + (uint32_t)r * (LDSA * 2) + c * 16,
                     g_embb + (size_t)(m0 + 128 + r) * E_ + c * 8);
            }
        }
        CP_COMMIT();

        // ---- mainloop: 128x128x128, full 32Mx64N warp tile ----
        float acc[2][8][4];
        #pragma unroll
        for (int i = 0; i < 2; i++)
            #pragma unroll
            for (int j = 0; j < 8; j++)
                #pragma unroll
                for (int k = 0; k < 4; k++) acc[i][j][k] = 0.f;

        #pragma unroll
        for (int ks = 0; ks < 8; ks++) {
            const uint32_t koff = (uint32_t)(ks * 16) * 2;
            uint32_t a0[4], a1[4], bb[4][4];
            ldsm4(a0, a_base + koff);
            ldsm4(a1, a_base + 16 * (LDSA * 2) + koff);
            #pragma unroll
            for (int nfp = 0; nfp < 4; nfp++)
                ldsm4(bb[nfp], b_rowb + (uint32_t)(nfp * 16) * (LDSA * 2) + koff);
            #pragma unroll
            for (int nfp = 0; nfp < 4; nfp++) {
                mma16816(acc[0][nfp * 2 + 0], a0, bb[nfp] + 0);
                mma16816(acc[0][nfp * 2 + 1], a0, bb[nfp] + 2);
                mma16816(acc[1][nfp * 2 + 0], a1, bb[nfp] + 0);
                mma16816(acc[1][nfp * 2 + 1], a1, bb[nfp] + 2);
            }
        }

        // ---- epilogue: ex2 sums + direct coalesced bf16 logit stores ----
        #pragma unroll
        for (int mf = 0; mf < 2; mf++)
            #pragma unroll
            for (int h = 0; h < 2; h++) {
                const int rl = wm * 32 + mf * 16 + h * 8 + qrow;
                const int rg = m0 + rl;
                float rsum = 0.f;
                #pragma unroll
                for (int sub = 0; sub < 2; sub++) {
                    uint32_t pk[4];
                    float t0 = 0.f, t1 = 0.f;
                    #pragma unroll
                    for (int jn = 0; jn < 4; jn++) {
                        const int j = sub * 4 + jn;
                        const int c = wn * 64 + j * 8 + (q << 1);
                        float x0 = acc[mf][j][h * 2 + 0] + bo_s[c];
                        float x1 = acc[mf][j][h * 2 + 1] + bo_s[c + 1];
                        t0 += ex2(x0);
                        t1 += ex2(x1);
                        __nv_bfloat162 pv = __floats2bfloat162_rn(x0, x1);
                        pk[jn] = *(uint32_t*)&pv;
                    }
                    rsum += t0 + t1;
                    const int gc = n0 + wn * 64 + sub * 32 + q * 8;
                    if (gc < V_)      // plain store: keep L2-warm for k_fix
                        *(uint4*)(g_logits + (size_t)rg * V_ + gc) =
                            make_uint4(pk[0], pk[1], pk[2], pk[3]);
                }
                rsum += __shfl_xor_sync(0xffffffffu, rsum, 1);
                rsum += __shfl_xor_sync(0xffffffffu, rsum, 2);
                if (q == 0) atomicAdd(&g_lsum[rg], rsum);   // REDG, no return
            }

        if (it + 1 < MT_) {
            CP_WAIT0();      // next A tile (overlapped with mainloop+epilogue)
            __syncthreads(); // A-buffer swap -- the ONLY per-tile barrier
        }
    }
}

// ---- LSE: log of accumulated sumexp; pad cols contribute exactly PAD_ ----
__global__ void k_lse2() {
    const int r = blockIdx.x * 256 + threadIdx.x;
    g_lse[r] = __logf(g_lsum[r] - PAD_);
}

// ---- streaming fixup: out = scaled_logit * ln2 - lse[row] ----
// grid (49, B_); one uint4 per thread. Rows processed DESCENDING so the
// L2-warm tail of g_logits (last-written rows) is read before eviction.
__global__ void __launch_bounds__(256) k_fix(float* __restrict__ out) {
    const int row = (B_ - 1) - blockIdx.y;
    const int chunk = blockIdx.x * 256 + threadIdx.x;   // uint4 index in row
    if (chunk >= V_ / 8) return;
    const float l = g_lse[row];
    const uint4 v = __ldcs((const uint4*)(g_logits + (size_t)row * V_) + chunk);
    const __nv_bfloat162* bp = (const __nv_bfloat162*)&v;
    float4 o0, o1;
    float2 f;
    f = __bfloat1622float2(bp[0]); o0.x = fmaf(f.x, LN2_, -l); o0.y = fmaf(f.y, LN2_, -l);
    f = __bfloat1622float2(bp[1]); o0.z = fmaf(f.x, LN2_, -l); o0.w = fmaf(f.y, LN2_, -l);
    f = __bfloat1622float2(bp[2]); o1.x = fmaf(f.x, LN2_, -l); o1.y = fmaf(f.y, LN2_, -l);
    f = __bfloat1622float2(bp[3]); o1.z = fmaf(f.x, LN2_, -l); o1.w = fmaf(f.y, LN2_, -l);
    float4* dst = (float4*)(out + (size_t)row * V_ + (size_t)chunk * 8);
    __stcs(dst + 0, o0);
    __stcs(dst + 1, o1);
}

extern "C" void kernel_launch(void* const* d_in, const int* in_sizes, int n_in,
                              void* d_out, int out_size) {
    const void*  cw = d_in[0];
    const float* Wc = (const float*)d_in[1];
    const float* bc = (const float*)d_in[2];
    const float* Wo = (const float*)d_in[3];
    const float* bo = (const float*)d_in[4];
    float* out = (float*)d_out;

    cudaFuncSetAttribute(k_gemm, cudaFuncAttributeMaxDynamicSharedMemorySize, SMEM_BYTES);

    k_zero<<<8, 256>>>();
    k_detect<<<1, 256>>>(cw);
    k_gather<<<B_, 128>>>(cw, Wc, bc);
    k_gemm<<<NT_, 256, SMEM_BYTES>>>(bo, Wo);
    k_lse2<<<8, 256>>>();
    k_fix<<<dim3((V_ / 8 + 255) / 256, B_), 256>>>(out);
}